// round 2
// baseline (speedup 1.0000x reference)
#include <cuda_runtime.h>

// Problem shape (fixed for this dataset entry)
constexpr int Bn = 8;
constexpr int S  = 1024;
constexpr int D  = 1024;
constexpr int R  = 256;

constexpr int M1 = Bn * S;   // 8192 rows for stage-1 GEMM
constexpr int N1 = 2 * R;    // 512: [left | right] concatenated
constexpr int K1 = D;        // 1024

// Scratch (device globals -- no allocations allowed)
__device__ float g_W[D * N1];    // packed weight: W[d][n] = n<R ? L[d][n] : Rm[n-R][d]
__device__ float g_P[M1 * N1];   // projections: P[i][0:256]=left, P[i][256:512]=right

// ---------------------------------------------------------------------------
// Pack [L | R^T] into one (D x 512) row-major weight so stage 1 is a single
// NN GEMM with contiguous B-tile loads.
// ---------------------------------------------------------------------------
__global__ void prep_w_kernel(const float* __restrict__ L,
                              const float* __restrict__ Rm) {
    int idx = blockIdx.x * 256 + threadIdx.x;
    if (idx >= D * N1) return;
    int d = idx / N1;
    int n = idx - d * N1;
    g_W[idx] = (n < R) ? L[d * R + n] : Rm[(n - R) * D + d];
}

// ---------------------------------------------------------------------------
// Stage 1: g_P (8192x512) = batch (8192x1024, row-major) @ g_W (1024x512)
// 128x128x8 tile, 256 threads, 8x8 microtile, double-buffered smem.
// ---------------------------------------------------------------------------
__global__ __launch_bounds__(256) void gemm1_kernel(const float* __restrict__ A) {
    __shared__ float As[2][8][128];   // [buf][k][m]
    __shared__ float Bs[2][8][128];   // [buf][k][n]

    const int tid = threadIdx.x;
    const int tx = tid & 15;        // 0..15 -> n microtile
    const int ty = tid >> 4;        // 0..15 -> m microtile
    const int bM = blockIdx.y * 128;
    const int bN = blockIdx.x * 128;

    // A-tile load mapping: 128 rows x 8 k, one float4 along K per thread
    const int aRow = tid >> 1;           // 0..127
    const int aK4  = (tid & 1) * 4;      // 0 or 4
    // B-tile load mapping: 8 k-rows x 128 n, one float4 along N per thread
    const int bKr  = tid >> 5;           // 0..7
    const int bN4  = (tid & 31) * 4;     // 0..124

    const float* Ag = A + (size_t)(bM + aRow) * K1 + aK4;
    const float* Wg = g_W + (size_t)bKr * N1 + bN + bN4;

    float acc[8][8];
    #pragma unroll
    for (int i = 0; i < 8; i++)
        #pragma unroll
        for (int j = 0; j < 8; j++) acc[i][j] = 0.0f;

    // Prologue: load k-tile 0 into buffer 0
    {
        float4 av = *(const float4*)(Ag);
        As[0][aK4 + 0][aRow] = av.x;
        As[0][aK4 + 1][aRow] = av.y;
        As[0][aK4 + 2][aRow] = av.z;
        As[0][aK4 + 3][aRow] = av.w;
        *(float4*)&Bs[0][bKr][bN4] = *(const float4*)(Wg);
    }
    __syncthreads();

    int buf = 0;
    for (int k0 = 0; k0 < K1; k0 += 8) {
        float4 av, bv;
        const bool more = (k0 + 8 < K1);
        if (more) {
            av = *(const float4*)(Ag + k0 + 8);
            bv = *(const float4*)(Wg + (size_t)(k0 + 8) * N1);
        }

        #pragma unroll
        for (int kk = 0; kk < 8; kk++) {
            float a[8], b[8];
            #pragma unroll
            for (int i = 0; i < 8; i++) a[i] = As[buf][kk][ty * 8 + i];
            #pragma unroll
            for (int j = 0; j < 8; j++) b[j] = Bs[buf][kk][tx * 8 + j];
            #pragma unroll
            for (int i = 0; i < 8; i++)
                #pragma unroll
                for (int j = 0; j < 8; j++)
                    acc[i][j] = fmaf(a[i], b[j], acc[i][j]);
        }

        if (more) {
            const int nb = buf ^ 1;
            As[nb][aK4 + 0][aRow] = av.x;
            As[nb][aK4 + 1][aRow] = av.y;
            As[nb][aK4 + 2][aRow] = av.z;
            As[nb][aK4 + 3][aRow] = av.w;
            *(float4*)&Bs[nb][bKr][bN4] = bv;
        }
        __syncthreads();
        buf ^= 1;
    }

    #pragma unroll
    for (int i = 0; i < 8; i++) {
        float* crow = g_P + (size_t)(bM + ty * 8 + i) * N1 + bN + tx * 8;
        *(float4*)(crow + 0) = make_float4(acc[i][0], acc[i][1], acc[i][2], acc[i][3]);
        *(float4*)(crow + 4) = make_float4(acc[i][4], acc[i][5], acc[i][6], acc[i][7]);
    }
}

// ---------------------------------------------------------------------------
// Stage 2 (per batch): C (1024x1024) = left (1024x256) @ right^T + bias
// left  = g_P[b*S + i][0:256]   (ld = 512)
// right = g_P[b*S + j][256:512] (ld = 512)
// NT GEMM, double-buffered smem.
// ---------------------------------------------------------------------------
__global__ __launch_bounds__(256) void gemm2_kernel(float* __restrict__ C,
                                                    const float* __restrict__ bias) {
    __shared__ float As[2][8][128];   // [buf][k][m] from left
    __shared__ float Bs[2][8][128];   // [buf][k][n] from right

    const int tid = threadIdx.x;
    const int tx = tid & 15;
    const int ty = tid >> 4;
    const int bM = blockIdx.y * 128;
    const int bN = blockIdx.x * 128;
    const int b  = blockIdx.z;

    const float* Pbase = g_P + (size_t)b * S * N1;
    float* Cb = C + (size_t)b * S * S;

    const int aRow = tid >> 1;
    const int aK4  = (tid & 1) * 4;

    const float* Ag = Pbase + (size_t)(bM + aRow) * N1 + aK4;        // left
    const float* Bg = Pbase + R + (size_t)(bN + aRow) * N1 + aK4;    // right

    float acc[8][8];
    #pragma unroll
    for (int i = 0; i < 8; i++)
        #pragma unroll
        for (int j = 0; j < 8; j++) acc[i][j] = 0.0f;

    // Prologue
    {
        float4 av = *(const float4*)(Ag);
        As[0][aK4 + 0][aRow] = av.x;
        As[0][aK4 + 1][aRow] = av.y;
        As[0][aK4 + 2][aRow] = av.z;
        As[0][aK4 + 3][aRow] = av.w;
        float4 bv = *(const float4*)(Bg);
        Bs[0][aK4 + 0][aRow] = bv.x;
        Bs[0][aK4 + 1][aRow] = bv.y;
        Bs[0][aK4 + 2][aRow] = bv.z;
        Bs[0][aK4 + 3][aRow] = bv.w;
    }
    __syncthreads();

    int buf = 0;
    for (int k0 = 0; k0 < R; k0 += 8) {
        float4 av, bv;
        const bool more = (k0 + 8 < R);
        if (more) {
            av = *(const float4*)(Ag + k0 + 8);
            bv = *(const float4*)(Bg + k0 + 8);
        }

        #pragma unroll
        for (int kk = 0; kk < 8; kk++) {
            float a[8], b2[8];
            #pragma unroll
            for (int i = 0; i < 8; i++) a[i] = As[buf][kk][ty * 8 + i];
            #pragma unroll
            for (int j = 0; j < 8; j++) b2[j] = Bs[buf][kk][tx * 8 + j];
            #pragma unroll
            for (int i = 0; i < 8; i++)
                #pragma unroll
                for (int j = 0; j < 8; j++)
                    acc[i][j] = fmaf(a[i], b2[j], acc[i][j]);
        }

        if (more) {
            const int nb = buf ^ 1;
            As[nb][aK4 + 0][aRow] = av.x;
            As[nb][aK4 + 1][aRow] = av.y;
            As[nb][aK4 + 2][aRow] = av.z;
            As[nb][aK4 + 3][aRow] = av.w;
            Bs[nb][aK4 + 0][aRow] = bv.x;
            Bs[nb][aK4 + 1][aRow] = bv.y;
            Bs[nb][aK4 + 2][aRow] = bv.z;
            Bs[nb][aK4 + 3][aRow] = bv.w;
        }
        __syncthreads();
        buf ^= 1;
    }

    const float bb = __ldg(bias);
    #pragma unroll
    for (int i = 0; i < 8; i++) {
        float* crow = Cb + (size_t)(bM + ty * 8 + i) * S + bN + tx * 8;
        *(float4*)(crow + 0) = make_float4(acc[i][0] + bb, acc[i][1] + bb,
                                           acc[i][2] + bb, acc[i][3] + bb);
        *(float4*)(crow + 4) = make_float4(acc[i][4] + bb, acc[i][5] + bb,
                                           acc[i][6] + bb, acc[i][7] + bb);
    }
}

extern "C" void kernel_launch(void* const* d_in, const int* in_sizes, int n_in,
                              void* d_out, int out_size) {
    const float* batch = (const float*)d_in[0];   // (8,1024,1024)
    const float* projL = (const float*)d_in[1];   // (1024,256)
    const float* projR = (const float*)d_in[2];   // (256,1024)
    const float* bias  = (const float*)d_in[3];   // (1,)
    float* out = (float*)d_out;                   // (8,1024,1024)

    // Pack weights
    prep_w_kernel<<<(D * N1 + 255) / 256, 256>>>(projL, projR);

    // Stage 1: projections (8192 x 512)
    {
        dim3 grid(N1 / 128, M1 / 128);  // (4, 64)
        gemm1_kernel<<<grid, 256>>>(batch);
    }

    // Stage 2: bilinear logits per batch
    {
        dim3 grid(S / 128, S / 128, Bn);  // (8, 8, 8)
        gemm2_kernel<<<grid, 256>>>(out, bias);
    }
}

// round 8
// speedup vs baseline: 1.6582x; 1.6582x over previous
#include <cuda_runtime.h>
#include <cstdint>

// Problem shape (fixed)
constexpr int Bn = 8;
constexpr int S  = 1024;
constexpr int Dd = 1024;
constexpr int R  = 256;

constexpr int M1 = Bn * S;   // 8192
constexpr int N1 = 2 * R;    // 512
constexpr int K1 = Dd;       // 1024

// Device scratch (no allocations allowed)
__device__ float g_Wt[N1 * K1];  // packed weight, K-major: Wt[n][k]
__device__ float g_P[M1 * N1];   // projections: P[i][0:256]=left, [256:512]=right

// ---------------------------------------------------------------------------
// Pack Wt[n][k] = n<R ? L[k][n] : Rm[n-R][k]
// ---------------------------------------------------------------------------
__global__ void prep_w_kernel(const float* __restrict__ L,
                              const float* __restrict__ Rm) {
    int idx = blockIdx.x * 256 + threadIdx.x;
    if (idx >= N1 * K1) return;
    int n = idx / K1;
    int k = idx - n * K1;
    g_Wt[idx] = (n < R) ? L[(size_t)k * R + n] : Rm[(size_t)(n - R) * Dd + k];
}

__device__ __forceinline__ uint32_t f2tf32(float v) {
    uint32_t u;
    asm("cvt.rna.tf32.f32 %0, %1;" : "=r"(u) : "f"(v));
    return u;
}

// ---------------------------------------------------------------------------
// Unified tf32 mma.sync GEMM: C(M,N) = A(M,K) @ B(N,K)^T [+ bias]
// A, B row-major, K contiguous. Block tile 128x128x32, 256 threads.
// Warp tile 64x32 (4 m16 x 4 n8 mma tiles). Double-buffered smem.
// ---------------------------------------------------------------------------
constexpr int KT   = 32;          // k-tile in floats
constexpr int LDSM = KT + 4;      // padded k-stride (36 floats, 16B-aligned)
constexpr int TILE_U32 = 128 * LDSM;          // 4608 u32 per operand buffer
constexpr int SMEM_BYTES = 4 * TILE_U32 * 4;  // A0,A1,B0,B1 = 73728 B

__global__ __launch_bounds__(256) void mma_gemm_kernel(
    const float* __restrict__ A, const float* __restrict__ B, float* __restrict__ C,
    int lda, int ldb, int ldc, int K,
    long long sA, long long sB, long long sC,
    const float* __restrict__ bias, int useBias)
{
    extern __shared__ uint32_t smem[];
    uint32_t* const As[2] = { smem,                smem + TILE_U32 };
    uint32_t* const Bs[2] = { smem + 2 * TILE_U32, smem + 3 * TILE_U32 };

    const int tid  = threadIdx.x;
    const int wid  = tid >> 5;
    const int lane = tid & 31;
    const int bM = blockIdx.y * 128;
    const int bN = blockIdx.x * 128;

    A += (long long)blockIdx.z * sA;
    B += (long long)blockIdx.z * sB;
    C += (long long)blockIdx.z * sC;

    // Warp layout: warpM = wid&1 (64 rows each), warpN = wid>>1 (32 cols each)
    const int warpRow = (wid & 1) * 64;
    const int warpCol = (wid >> 1) * 32;
    const int g4 = lane >> 2;   // 0..7
    const int tg = lane & 3;    // 0..3

    // Global->smem load mapping: row = tid>>1, two threads cover 32 floats/row
    const int gRow  = tid >> 1;
    const int gCol0 = (tid & 1) * 16;
    const float* Ag = A + (size_t)(bM + gRow) * lda + gCol0;
    const float* Bg = B + (size_t)(bN + gRow) * ldb + gCol0;
    const int sBase = gRow * LDSM + gCol0;

    // Fragment smem offsets
    const int aOff = (warpRow + g4) * LDSM + tg;
    const int bOff = (warpCol + g4) * LDSM + tg;

    float acc[4][4][4];
    #pragma unroll
    for (int mi = 0; mi < 4; mi++)
        #pragma unroll
        for (int ni = 0; ni < 4; ni++)
            #pragma unroll
            for (int r = 0; r < 4; r++) acc[mi][ni][r] = 0.0f;

    // Prologue: load k-tile 0 into buffer 0 (convert to tf32 at store)
    {
        #pragma unroll
        for (int j = 0; j < 4; j++) {
            float4 av = *(const float4*)(Ag + j * 4);
            float4 bv = *(const float4*)(Bg + j * 4);
            uint32_t* a = &As[0][sBase + j * 4];
            uint32_t* b = &Bs[0][sBase + j * 4];
            a[0] = f2tf32(av.x); a[1] = f2tf32(av.y); a[2] = f2tf32(av.z); a[3] = f2tf32(av.w);
            b[0] = f2tf32(bv.x); b[1] = f2tf32(bv.y); b[2] = f2tf32(bv.z); b[3] = f2tf32(bv.w);
        }
    }
    __syncthreads();

    const int ktiles = K / KT;
    int buf = 0;
    for (int kt = 0; kt < ktiles; kt++) {
        // Prefetch next k-tile into registers
        float4 pa[4], pb[4];
        const bool more = (kt + 1 < ktiles);
        if (more) {
            const float* An = Ag + (kt + 1) * KT;
            const float* Bn2 = Bg + (kt + 1) * KT;
            #pragma unroll
            for (int j = 0; j < 4; j++) { pa[j] = *(const float4*)(An + j * 4);
                                          pb[j] = *(const float4*)(Bn2 + j * 4); }
        }

        // Compute: 4 k-steps of 8
        const uint32_t* Ab = As[buf];
        const uint32_t* Bb = Bs[buf];
        #pragma unroll
        for (int kk = 0; kk < 4; kk++) {
            uint32_t af[4][4];
            #pragma unroll
            for (int mi = 0; mi < 4; mi++) {
                const int base = aOff + mi * 16 * LDSM + kk * 8;
                af[mi][0] = Ab[base];
                af[mi][1] = Ab[base + 8 * LDSM];
                af[mi][2] = Ab[base + 4];
                af[mi][3] = Ab[base + 8 * LDSM + 4];
            }
            uint32_t bf[4][2];
            #pragma unroll
            for (int ni = 0; ni < 4; ni++) {
                const int base = bOff + ni * 8 * LDSM + kk * 8;
                bf[ni][0] = Bb[base];
                bf[ni][1] = Bb[base + 4];
            }
            #pragma unroll
            for (int mi = 0; mi < 4; mi++)
                #pragma unroll
                for (int ni = 0; ni < 4; ni++) {
                    asm volatile(
                        "mma.sync.aligned.m16n8k8.row.col.f32.tf32.tf32.f32 "
                        "{%0,%1,%2,%3}, {%4,%5,%6,%7}, {%8,%9}, {%0,%1,%2,%3};"
                        : "+f"(acc[mi][ni][0]), "+f"(acc[mi][ni][1]),
                          "+f"(acc[mi][ni][2]), "+f"(acc[mi][ni][3])
                        : "r"(af[mi][0]), "r"(af[mi][1]), "r"(af[mi][2]), "r"(af[mi][3]),
                          "r"(bf[ni][0]), "r"(bf[ni][1]));
                }
        }

        // Store prefetched tile into other buffer
        if (more) {
            uint32_t* An = As[buf ^ 1];
            uint32_t* Bn2 = Bs[buf ^ 1];
            #pragma unroll
            for (int j = 0; j < 4; j++) {
                uint32_t* a = &An[sBase + j * 4];
                uint32_t* b = &Bn2[sBase + j * 4];
                a[0] = f2tf32(pa[j].x); a[1] = f2tf32(pa[j].y);
                a[2] = f2tf32(pa[j].z); a[3] = f2tf32(pa[j].w);
                b[0] = f2tf32(pb[j].x); b[1] = f2tf32(pb[j].y);
                b[2] = f2tf32(pb[j].z); b[3] = f2tf32(pb[j].w);
            }
        }
        __syncthreads();
        buf ^= 1;
    }

    // Epilogue
    const float bb = useBias ? __ldg(bias) : 0.0f;
    #pragma unroll
    for (int mi = 0; mi < 4; mi++) {
        const int row0 = bM + warpRow + mi * 16 + g4;
        #pragma unroll
        for (int ni = 0; ni < 4; ni++) {
            const int col = bN + warpCol + ni * 8 + tg * 2;
            float2 v0 = make_float2(acc[mi][ni][0] + bb, acc[mi][ni][1] + bb);
            float2 v1 = make_float2(acc[mi][ni][2] + bb, acc[mi][ni][3] + bb);
            *(float2*)(C + (size_t)row0 * ldc + col) = v0;
            *(float2*)(C + (size_t)(row0 + 8) * ldc + col) = v1;
        }
    }
}

// ---------------------------------------------------------------------------
extern "C" void kernel_launch(void* const* d_in, const int* in_sizes, int n_in,
                              void* d_out, int out_size) {
    const float* batch = (const float*)d_in[0];   // (8,1024,1024)
    const float* projL = (const float*)d_in[1];   // (1024,256)
    const float* projR = (const float*)d_in[2];   // (256,1024)
    const float* bias  = (const float*)d_in[3];   // (1,)
    float* out = (float*)d_out;                   // (8,1024,1024)

    // Idempotent, legal during stream capture; no static state allowed here.
    cudaFuncSetAttribute(mma_gemm_kernel,
                         cudaFuncAttributeMaxDynamicSharedMemorySize, SMEM_BYTES);

    void *pW = nullptr, *pP = nullptr;
    cudaGetSymbolAddress(&pW, g_Wt);
    cudaGetSymbolAddress(&pP, g_P);
    float* Wt = (float*)pW;
    float* P  = (float*)pP;

    // Pack weights (K-major)
    prep_w_kernel<<<(N1 * K1 + 255) / 256, 256>>>(projL, projR);

    // Stage 1: g_P (8192x512) = batch (8192x1024) @ Wt(512x1024)^T
    {
        dim3 grid(N1 / 128, M1 / 128, 1);   // (4, 64, 1)
        mma_gemm_kernel<<<grid, 256, SMEM_BYTES>>>(
            batch, Wt, P, K1, K1, N1, K1, 0, 0, 0, nullptr, 0);
    }

    // Stage 2 (per batch): out_b (1024x1024) = left_b (1024x256) @ right_b^T + bias
    {
        dim3 grid(S / 128, S / 128, Bn);    // (8, 8, 8)
        mma_gemm_kernel<<<grid, 256, SMEM_BYTES>>>(
            P, P + R, out, N1, N1, S, R,
            (long long)S * N1, (long long)S * N1, (long long)S * S,
            bias, 1);
    }
}

// round 10
// speedup vs baseline: 2.2447x; 1.3537x over previous
#include <cuda_runtime.h>
#include <cstdint>

// Problem shape (fixed)
constexpr int Bn = 8;
constexpr int S  = 1024;
constexpr int Dd = 1024;
constexpr int R  = 256;

constexpr int M1 = Bn * S;   // 8192
constexpr int N1 = 2 * R;    // 512
constexpr int K1 = Dd;       // 1024

// Device scratch (no allocations allowed). All tf32-pre-rounded fp32.
__device__ float g_Wt[N1 * K1];   // packed weight, K-major: Wt[n][k]
__device__ float g_Bt[M1 * K1];   // tf32-rounded copy of batch
__device__ float g_P [M1 * N1];   // projections (tf32-rounded at epilogue)

__device__ __forceinline__ float tf32r(float v) {
    uint32_t u;
    asm("cvt.rna.tf32.f32 %0, %1;" : "=r"(u) : "f"(v));
    return __uint_as_float(u);
}

// ---------------------------------------------------------------------------
// prep_L: Wt[n][k] = round(L[k][n]) for n<R  (tiled transpose, coalesced)
// ---------------------------------------------------------------------------
__global__ void prep_L_kernel(const float* __restrict__ L) {
    __shared__ float t[32][33];
    const int tx = threadIdx.x, ty = threadIdx.y;      // 32 x 8
    const int n0 = blockIdx.x * 32;                     // n tile
    const int k0 = blockIdx.y * 32;                     // k tile
    #pragma unroll
    for (int j = 0; j < 32; j += 8)
        t[ty + j][tx] = L[(size_t)(k0 + ty + j) * R + n0 + tx];  // t[k][n]
    __syncthreads();
    #pragma unroll
    for (int j = 0; j < 32; j += 8)
        g_Wt[(size_t)(n0 + ty + j) * K1 + k0 + tx] = tf32r(t[tx][ty + j]);
}

// ---------------------------------------------------------------------------
// round-copy: dst[i] = tf32_round(src[i]), float4-vectorized
// ---------------------------------------------------------------------------
__global__ void round_copy_kernel(const float4* __restrict__ src,
                                  float4* __restrict__ dst, int n4) {
    int i = blockIdx.x * 256 + threadIdx.x;
    if (i >= n4) return;
    float4 v = src[i];
    v.x = tf32r(v.x); v.y = tf32r(v.y); v.z = tf32r(v.z); v.w = tf32r(v.w);
    dst[i] = v;
}

// ---------------------------------------------------------------------------
// Async tf32 GEMM: C(M,N) = A(M,K) @ B(N,K)^T [+bias] [round output]
// Inputs pre-rounded to tf32. Block 128x128x32, 256 thr, warp 64x32.
// 3-stage cp.async ring, ldmatrix.x4 fragment feeds.
// ---------------------------------------------------------------------------
constexpr int LDSF  = 36;                   // floats per smem row (16B-pad)
constexpr int TILEF = 128 * LDSF;           // 4608 floats per operand tile
constexpr int STAGEF = 2 * TILEF;           // A + B per stage
constexpr int STAGES = 3;
constexpr int SMEM_BYTES = STAGES * STAGEF * 4;   // 110592

#define LDSM4(r0, r1, r2, r3, addr)                                        \
    asm volatile("ldmatrix.sync.aligned.m8n8.x4.shared.b16 "               \
                 "{%0,%1,%2,%3}, [%4];"                                    \
                 : "=r"(r0), "=r"(r1), "=r"(r2), "=r"(r3) : "r"(addr))

__global__ __launch_bounds__(256, 2) void mma_gemm_kernel(
    const float* __restrict__ A, const float* __restrict__ B, float* __restrict__ C,
    int lda, int ldb, int ldc, int K,
    long long sA, long long sB, long long sC,
    const float* __restrict__ bias, int useBias, int roundOut)
{
    extern __shared__ float smem[];
    const uint32_t sb = (uint32_t)__cvta_generic_to_shared(smem);

    const int tid  = threadIdx.x;
    const int wid  = tid >> 5;
    const int lane = tid & 31;
    const int bM = blockIdx.y * 128;
    const int bN = blockIdx.x * 128;

    A += (long long)blockIdx.z * sA;
    B += (long long)blockIdx.z * sB;
    C += (long long)blockIdx.z * sC;

    const int warpRow = (wid & 1) * 64;
    const int warpCol = (wid >> 1) * 32;
    const int g4 = lane >> 2;
    const int tg = lane & 3;

    // cp.async mapping: row = tid>>1, half-row of 16 floats
    const int cRow  = tid >> 1;
    const int cCol  = (tid & 1) * 16;
    const float* gA = A + (size_t)(bM + cRow) * lda + cCol;
    const float* gB = B + (size_t)(bN + cRow) * ldb + cCol;
    const uint32_t stA = sb + (uint32_t)(cRow * LDSF + cCol) * 4;
    const uint32_t stB = stA + TILEF * 4;

    // ldmatrix per-lane source addresses
    const int laRow = warpRow + (lane & 7) + ((lane >> 3) & 1) * 8;
    const int laCol = (lane >> 4) * 4;
    const int lbRow = warpCol + (lane & 7) + (lane >> 4) * 8;
    const int lbCol = ((lane >> 3) & 1) * 4;
    const uint32_t laBase = sb + (uint32_t)(laRow * LDSF + laCol) * 4;
    const uint32_t lbBase = sb + (uint32_t)(TILEF + lbRow * LDSF + lbCol) * 4;

    float acc[4][4][4];
    #pragma unroll
    for (int mi = 0; mi < 4; mi++)
        #pragma unroll
        for (int ni = 0; ni < 4; ni++)
            #pragma unroll
            for (int r = 0; r < 4; r++) acc[mi][ni][r] = 0.0f;

    const int n = K >> 5;

    // --- issue helper (macro to keep addresses simple) ---
    #define ISSUE_TILE(stage, kt) do {                                         \
        const float* _ga = gA + (kt) * 32;                                     \
        const float* _gb = gB + (kt) * 32;                                     \
        uint32_t _da = stA + (uint32_t)(stage) * (STAGEF * 4);                 \
        uint32_t _db = stB + (uint32_t)(stage) * (STAGEF * 4);                 \
        _Pragma("unroll")                                                      \
        for (int _j = 0; _j < 4; _j++) {                                       \
            asm volatile("cp.async.cg.shared.global [%0], [%1], 16;"           \
                         :: "r"(_da + _j * 16), "l"(_ga + _j * 4));            \
            asm volatile("cp.async.cg.shared.global [%0], [%1], 16;"           \
                         :: "r"(_db + _j * 16), "l"(_gb + _j * 4));            \
        }                                                                      \
        asm volatile("cp.async.commit_group;");                                \
    } while (0)

    // Prologue: stages 0,1
    ISSUE_TILE(0, 0);
    ISSUE_TILE(1, 1);

    int stage = 0;
    for (int kt = 0; kt < n; kt++) {
        if (kt == n - 1) { asm volatile("cp.async.wait_group 0;" ::: "memory"); }
        else             { asm volatile("cp.async.wait_group 1;" ::: "memory"); }
        __syncthreads();

        if (kt + 2 < n) {
            int ns = stage + 2; if (ns >= STAGES) ns -= STAGES;
            ISSUE_TILE(ns, kt + 2);
        }

        const uint32_t aB = laBase + (uint32_t)stage * (STAGEF * 4);
        const uint32_t bB = lbBase + (uint32_t)stage * (STAGEF * 4);
        #pragma unroll
        for (int kk = 0; kk < 4; kk++) {
            uint32_t af[4][4];
            #pragma unroll
            for (int mi = 0; mi < 4; mi++)
                LDSM4(af[mi][0], af[mi][1], af[mi][2], af[mi][3],
                      aB + (uint32_t)(mi * 16 * LDSF + kk * 8) * 4);
            uint32_t bf[4][2];
            #pragma unroll
            for (int p = 0; p < 2; p++)
                LDSM4(bf[2 * p][0], bf[2 * p][1], bf[2 * p + 1][0], bf[2 * p + 1][1],
                      bB + (uint32_t)(p * 16 * LDSF + kk * 8) * 4);
            #pragma unroll
            for (int mi = 0; mi < 4; mi++)
                #pragma unroll
                for (int ni = 0; ni < 4; ni++) {
                    asm volatile(
                        "mma.sync.aligned.m16n8k8.row.col.f32.tf32.tf32.f32 "
                        "{%0,%1,%2,%3}, {%4,%5,%6,%7}, {%8,%9}, {%0,%1,%2,%3};"
                        : "+f"(acc[mi][ni][0]), "+f"(acc[mi][ni][1]),
                          "+f"(acc[mi][ni][2]), "+f"(acc[mi][ni][3])
                        : "r"(af[mi][0]), "r"(af[mi][1]), "r"(af[mi][2]), "r"(af[mi][3]),
                          "r"(bf[ni][0]), "r"(bf[ni][1]));
                }
        }
        stage++; if (stage >= STAGES) stage = 0;
    }
    #undef ISSUE_TILE

    // Epilogue
    const float bb = useBias ? __ldg(bias) : 0.0f;
    #pragma unroll
    for (int mi = 0; mi < 4; mi++) {
        const int row0 = bM + warpRow + mi * 16 + g4;
        #pragma unroll
        for (int ni = 0; ni < 4; ni++) {
            const int col = bN + warpCol + ni * 8 + tg * 2;
            float v0 = acc[mi][ni][0] + bb, v1 = acc[mi][ni][1] + bb;
            float v2 = acc[mi][ni][2] + bb, v3 = acc[mi][ni][3] + bb;
            if (roundOut) { v0 = tf32r(v0); v1 = tf32r(v1); v2 = tf32r(v2); v3 = tf32r(v3); }
            *(float2*)(C + (size_t)row0 * ldc + col)       = make_float2(v0, v1);
            *(float2*)(C + (size_t)(row0 + 8) * ldc + col) = make_float2(v2, v3);
        }
    }
}

// ---------------------------------------------------------------------------
extern "C" void kernel_launch(void* const* d_in, const int* in_sizes, int n_in,
                              void* d_out, int out_size) {
    const float* batch = (const float*)d_in[0];   // (8,1024,1024)
    const float* projL = (const float*)d_in[1];   // (1024,256)
    const float* projR = (const float*)d_in[2];   // (256,1024)
    const float* bias  = (const float*)d_in[3];   // (1,)
    float* out = (float*)d_out;                   // (8,1024,1024)

    cudaFuncSetAttribute(mma_gemm_kernel,
                         cudaFuncAttributeMaxDynamicSharedMemorySize, SMEM_BYTES);

    void *pW = nullptr, *pP = nullptr, *pBt = nullptr;
    cudaGetSymbolAddress(&pW, g_Wt);
    cudaGetSymbolAddress(&pP, g_P);
    cudaGetSymbolAddress(&pBt, g_Bt);
    float* Wt = (float*)pW;
    float* P  = (float*)pP;
    float* Bt = (float*)pBt;

    // Prep: Wt top half = L^T (rounded), bottom half = R (rounded), batch rounded
    {
        dim3 grid(R / 32, K1 / 32);
        prep_L_kernel<<<grid, dim3(32, 8)>>>(projL);
    }
    {
        int n4 = (R * Dd) / 4;   // 65536
        round_copy_kernel<<<(n4 + 255) / 256, 256>>>(
            (const float4*)projR, (float4*)(Wt + (size_t)R * K1), n4);
    }
    {
        int n4 = (M1 * K1) / 4;  // 2M
        round_copy_kernel<<<(n4 + 255) / 256, 256>>>(
            (const float4*)batch, (float4*)Bt, n4);
    }

    // Stage 1: g_P (8192x512) = Bt (8192x1024) @ Wt(512x1024)^T, rounded output
    {
        dim3 grid(N1 / 128, M1 / 128, 1);   // (4, 64, 1)
        mma_gemm_kernel<<<grid, 256, SMEM_BYTES>>>(
            Bt, Wt, P, K1, K1, N1, K1, 0, 0, 0, nullptr, 0, 1);
    }

    // Stage 2 (per batch): out_b = left_b (1024x256) @ right_b^T + bias
    {
        dim3 grid(S / 128, S / 128, Bn);    // (8, 8, 8)
        mma_gemm_kernel<<<grid, 256, SMEM_BYTES>>>(
            P, P + R, out, N1, N1, S, R,
            (long long)S * N1, (long long)S * N1, (long long)S * S,
            bias, 1, 0);
    }
}